// round 10
// baseline (speedup 1.0000x reference)
#include <cuda_runtime.h>
#include <cstdint>

// ViewControlPreprocessor (non-causal path), GB300 sm_103a.
//   out[r, :3072]           = hidden[r, :]                       (f32)
//   out[r, 3072 + p*16 + c] = vcc[max(4*(r%21)+p-8, 0), c]
//
// R10 experiment: 256-bit (v8.f32) global loads/stores — sm_100+ feature.
// Everything else identical to the R7/R9 optimum (256 thr, 64B in flight
// per thread, predicate-free exact grid, streaming hints).
// Units below are f8 = 8 floats = 32 bytes.

static constexpr int T_Q     = 21;
static constexpr int ROWS    = 1536 * 21;          // 32256
static constexpr int HID_F8  = 3072 / 8;           // 384 f8 per row (hidden)
static constexpr int ROW_F8  = 400;                // f8 per output row
static constexpr int PAD_T   = 8;
static constexpr long long TOTAL_F8 = (long long)ROWS * ROW_F8;  // 12,902,400
static constexpr int THREADS = 256;
static constexpr int UNROLL  = 2;
// 12,902,400 / (256*2) = 25200 exactly -> predicate-free grid.
static constexpr int BLOCKS  = (int)(TOTAL_F8 / (THREADS * UNROLL));

struct F8 { float v[8]; };

__device__ __forceinline__ F8 ldg256_cs(const float* p)   // streaming read
{
    F8 r;
    asm volatile("ld.global.cs.v8.f32 {%0,%1,%2,%3,%4,%5,%6,%7}, [%8];"
        : "=f"(r.v[0]), "=f"(r.v[1]), "=f"(r.v[2]), "=f"(r.v[3]),
          "=f"(r.v[4]), "=f"(r.v[5]), "=f"(r.v[6]), "=f"(r.v[7])
        : "l"(p));
    return r;
}

__device__ __forceinline__ F8 ldg256_nc(const float* p)   // cached table read
{
    F8 r;
    asm volatile("ld.global.nc.v8.f32 {%0,%1,%2,%3,%4,%5,%6,%7}, [%8];"
        : "=f"(r.v[0]), "=f"(r.v[1]), "=f"(r.v[2]), "=f"(r.v[3]),
          "=f"(r.v[4]), "=f"(r.v[5]), "=f"(r.v[6]), "=f"(r.v[7])
        : "l"(p));
    return r;
}

__device__ __forceinline__ void stg256_cs(float* p, const F8& r)
{
    asm volatile("st.global.cs.v8.f32 [%0], {%1,%2,%3,%4,%5,%6,%7,%8};"
        :: "l"(p),
           "f"(r.v[0]), "f"(r.v[1]), "f"(r.v[2]), "f"(r.v[3]),
           "f"(r.v[4]), "f"(r.v[5]), "f"(r.v[6]), "f"(r.v[7])
        : "memory");
}

__device__ __forceinline__ F8 fetch_one(const float* __restrict__ hidden,
                                        const float* __restrict__ vcc,
                                        int i)   // i = f8 index into output
{
    int row  = i / ROW_F8;          // compile-time-constant divide -> IMAD magic
    int col8 = i - row * ROW_F8;

    if (col8 < HID_F8) {
        // hidden f8 index = row*384 + col8 = i - 16*row
        return ldg256_cs(hidden + (size_t)(i - 16 * row) * 8);
    } else {
        int c8 = col8 - HID_F8;      // 0..15
        int p  = c8 >> 1;            // PAD_T slot (0..7)
        int q  = c8 & 1;             // which 32B half of the 64B channel row
        int t  = row % T_Q;
        int j  = 4 * t + p;          // padded index 0..88
        int src = (j < PAD_T) ? 0 : (j - PAD_T);
        return ldg256_nc(vcc + (size_t)(src * 2 + q) * 8);  // 5KB L1 table
    }
}

__global__ void __launch_bounds__(THREADS)
vcp_fuse_kernel(const float* __restrict__ hidden,
                const float* __restrict__ vcc,
                float* __restrict__ out)
{
    // Block covers 512 consecutive f8 (16KB dst span); each 256-thread sweep
    // is a contiguous 8KB span, 1024B per warp instruction. Some warps
    // straddle the hidden/tail boundary (400 % 32 = 16) -> both predicated
    // branches execute there; extra cost is a few ALU ops + an L1-hit load.
    int base = blockIdx.x * (THREADS * UNROLL) + threadIdx.x;

    F8 v[UNROLL];
    #pragma unroll
    for (int u = 0; u < UNROLL; u++) {
        v[u] = fetch_one(hidden, vcc, base + u * THREADS);
    }
    #pragma unroll
    for (int u = 0; u < UNROLL; u++) {
        stg256_cs(out + (size_t)(base + u * THREADS) * 8, v[u]);
    }
}

extern "C" void kernel_launch(void* const* d_in, const int* in_sizes, int n_in,
                              void* d_out, int out_size)
{
    const float* hidden = (const float*)d_in[0];
    const float* vcc    = (const float*)d_in[1];
    float* out = (float*)d_out;

    vcp_fuse_kernel<<<BLOCKS, THREADS>>>(hidden, vcc, out);
}

// round 11
// speedup vs baseline: 1.0134x; 1.0134x over previous
#include <cuda_runtime.h>
#include <cstdint>

// ViewControlPreprocessor (non-causal path), GB300 sm_103a.  FINAL.
//   hidden_states: (1536, 21, 3072) f32
//   view_control_condition: (1, 81, 16) f32  -> 5KB L1-resident table
//   output: (1536, 21, 3200) f32
//
//   out[r, :3072]            = hidden[r, :]
//   out[r, 3072 + p*16 + c]  = vcc[max(4*(r%21)+p-8, 0), c],  p in [0,8)
//
// Roofline: compulsory 396MB read + 413MB write. Measured GB300 mixed-R/W
// plateau ~6.73 TB/s (~85% of 8TB/s spec). Full lever sweep (kernel us):
//   256thr/U4 float4 predicate-free: 112.1-112.4 @ 84.9% DRAM  <- THIS
//   256thr/U8 float4:                113.1 @ 84.1%
//   128thr/U4 float4:                113.6 @ 83.8%
//   256thr/U2 v8.f32 (256-bit ops):  113.8 @ 83.6%  (fewer wavefronts ->
//                                     worse DRAM request interleave)
//   persistent 888-block grid:       120.8 @ 79.3%  (tail starvation)
//   copy-engine memcpy2D:            ~390  (row-segmented CE path)
// Residual ~15% vs spec is HBM R/W turnaround at the controller, invariant
// under MLP, occupancy, access width, and transport path: not addressable
// from SASS. This kernel is at its hardware roofline.

static constexpr int T_Q     = 21;
static constexpr int ROWS    = 1536 * 21;          // 32256
static constexpr int HID_F4  = 3072 / 4;           // 768 float4 per row (hidden)
static constexpr int ROW_F4  = 800;                // float4 per output row
static constexpr int PAD_T   = 8;
static constexpr long long TOTAL_F4 = (long long)ROWS * ROW_F4;  // 25,804,800
static constexpr int THREADS = 256;
static constexpr int UNROLL  = 4;
// 25,804,800 / (256*4) = 25200 exactly -> predicate-free grid.
static constexpr int BLOCKS  = (int)(TOTAL_F4 / (THREADS * UNROLL));

__device__ __forceinline__ float4 fetch_one(const float4* __restrict__ hidden,
                                            const float4* __restrict__ vcc,
                                            int i)
{
    int row  = i / ROW_F4;          // compile-time-constant divide -> IMAD magic
    int col4 = i - row * ROW_F4;

    if (col4 < HID_F4) {
        // hidden_idx = row*768 + col4 = i - 32*row
        return __ldcs(&hidden[i - 32 * row]);   // streaming: read exactly once
    } else {
        int c4 = col4 - HID_F4;      // 0..31
        int p  = c4 >> 2;            // PAD_T slot (0..7)
        int q  = c4 & 3;             // float4 within 16-float channel row
        int t  = row % T_Q;          // compile-time-constant mod
        int j  = 4 * t + p;          // padded index 0..88
        int src = (j < PAD_T) ? 0 : (j - PAD_T);
        return __ldg(&vcc[src * 4 + q]);   // 5KB table, L1-resident
    }
}

__global__ void __launch_bounds__(THREADS)
vcp_fuse_kernel(const float4* __restrict__ hidden,
                const float4* __restrict__ vcc,
                float4* __restrict__ out)
{
    // Block covers 1024 consecutive float4 (16KB dst span); each 256-thread
    // sweep is a contiguous, perfectly coalesced 4KB span. Warp spans never
    // straddle the hidden/tail boundary (768 and 800 are multiples of 32)
    // -> zero intra-warp divergence.
    int base = blockIdx.x * (THREADS * UNROLL) + threadIdx.x;

    float4 v[UNROLL];
    // Batch all loads first (per-thread MLP = 4), then all stores.
    #pragma unroll
    for (int u = 0; u < UNROLL; u++) {
        v[u] = fetch_one(hidden, vcc, base + u * THREADS);
    }
    #pragma unroll
    for (int u = 0; u < UNROLL; u++) {
        __stcs(&out[base + u * THREADS], v[u]);   // streaming store: never re-read
    }
}

extern "C" void kernel_launch(void* const* d_in, const int* in_sizes, int n_in,
                              void* d_out, int out_size)
{
    const float4* hidden = (const float4*)d_in[0];
    const float4* vcc    = (const float4*)d_in[1];
    float4* out = (float4*)d_out;

    vcp_fuse_kernel<<<BLOCKS, THREADS>>>(hidden, vcc, out);
}